// round 2
// baseline (speedup 1.0000x reference)
#include <cuda_runtime.h>
#include <cstddef>

// x: (8, 16, 3, 256, 256) fp32 contiguous; out: (128, 2, 256, 256) fp32
// out[bl, ch, :] = plane(bl*3) - plane((bl-1)*3), zero when bl%16==0, both ch identical.

static constexpr int HW4   = 16384;        // 256*256/4 float4 per plane
static constexpr int V     = 4;            // float4 per thread
static constexpr int HWV   = HW4 / V;      // 4096 thread-chunks per plane
static constexpr int BL    = 128;
static constexpr int TOTALT = BL * HWV;    // 524288 threads

__global__ __launch_bounds__(256) void dummyflow_diff_kernel(
    const float4* __restrict__ x, float4* __restrict__ out)
{
    int idx = blockIdx.x * blockDim.x + threadIdx.x;
    if (idx >= TOTALT) return;

    int bl = idx >> 12;                 // idx / HWV
    int hw = (idx & (HWV - 1)) * V;     // float4 offset within plane
    int l  = bl & 15;

    size_t obase = (size_t)(bl * 2) * HW4 + hw;

    if (l == 0) {
        float4 z = make_float4(0.f, 0.f, 0.f, 0.f);
        #pragma unroll
        for (int i = 0; i < V; i++) {
            out[obase + i]       = z;
            out[obase + HW4 + i] = z;
        }
        return;
    }

    size_t cur  = (size_t)(bl * 3)       * HW4 + hw;
    size_t prev = (size_t)((bl - 1) * 3) * HW4 + hw;

    // Front-batch all 8 loads for maximum MLP
    float4 a0 = x[cur + 0];
    float4 a1 = x[cur + 1];
    float4 a2 = x[cur + 2];
    float4 a3 = x[cur + 3];
    float4 p0 = x[prev + 0];
    float4 p1 = x[prev + 1];
    float4 p2 = x[prev + 2];
    float4 p3 = x[prev + 3];

    float4 v0 = make_float4(a0.x - p0.x, a0.y - p0.y, a0.z - p0.z, a0.w - p0.w);
    float4 v1 = make_float4(a1.x - p1.x, a1.y - p1.y, a1.z - p1.z, a1.w - p1.w);
    float4 v2 = make_float4(a2.x - p2.x, a2.y - p2.y, a2.z - p2.z, a2.w - p2.w);
    float4 v3 = make_float4(a3.x - p3.x, a3.y - p3.y, a3.z - p3.z, a3.w - p3.w);

    out[obase + 0] = v0;
    out[obase + 1] = v1;
    out[obase + 2] = v2;
    out[obase + 3] = v3;
    out[obase + HW4 + 0] = v0;
    out[obase + HW4 + 1] = v1;
    out[obase + HW4 + 2] = v2;
    out[obase + HW4 + 3] = v3;
}

extern "C" void kernel_launch(void* const* d_in, const int* in_sizes, int n_in,
                              void* d_out, int out_size)
{
    const float4* x = (const float4*)d_in[0];
    float4* out = (float4*)d_out;

    int threads = 256;
    int blocks = TOTALT / threads;   // 2048
    dummyflow_diff_kernel<<<blocks, threads>>>(x, out);
}

// round 3
// speedup vs baseline: 1.5674x; 1.5674x over previous
#include <cuda_runtime.h>
#include <cstddef>

// x: (8, 16, 3, 256, 256) fp32; out: (128, 2, 256, 256) fp32
// out[bl, ch, :] = plane(bl*3) - plane((bl-1)*3); zero when bl%16==0; ch0==ch1.

static constexpr int HW4    = 16384;       // 256*256/4 float4 per plane
static constexpr int V      = 4;           // float4 per thread (ILP)
static constexpr int HWV    = HW4 / V;     // 4096 threads per plane
static constexpr int BL     = 128;
static constexpr int TOTALT = BL * HWV;    // 524288 threads

__global__ __launch_bounds__(256) void dummyflow_diff_kernel(
    const float4* __restrict__ x, float4* __restrict__ out)
{
    int idx = blockIdx.x * blockDim.x + threadIdx.x;
    if (idx >= TOTALT) return;

    int bl = idx >> 12;               // idx / HWV
    int j  = idx & (HWV - 1);         // within-plane thread index (coalesced)
    int l  = bl & 15;

    size_t obase = (size_t)(bl * 2) * HW4 + j;

    if (l == 0) {
        float4 z = make_float4(0.f, 0.f, 0.f, 0.f);
        #pragma unroll
        for (int k = 0; k < V; k++) {
            out[obase + k * HWV]       = z;
            out[obase + k * HWV + HW4] = z;
        }
        return;
    }

    size_t cur  = (size_t)(bl * 3)       * HW4 + j;
    size_t prev = (size_t)((bl - 1) * 3) * HW4 + j;

    // 8 independent, fully-coalesced LDG.128 front-batched for MLP
    float4 a0 = x[cur  + 0 * HWV];
    float4 a1 = x[cur  + 1 * HWV];
    float4 a2 = x[cur  + 2 * HWV];
    float4 a3 = x[cur  + 3 * HWV];
    float4 p0 = x[prev + 0 * HWV];
    float4 p1 = x[prev + 1 * HWV];
    float4 p2 = x[prev + 2 * HWV];
    float4 p3 = x[prev + 3 * HWV];

    float4 v0 = make_float4(a0.x - p0.x, a0.y - p0.y, a0.z - p0.z, a0.w - p0.w);
    float4 v1 = make_float4(a1.x - p1.x, a1.y - p1.y, a1.z - p1.z, a1.w - p1.w);
    float4 v2 = make_float4(a2.x - p2.x, a2.y - p2.y, a2.z - p2.z, a2.w - p2.w);
    float4 v3 = make_float4(a3.x - p3.x, a3.y - p3.y, a3.z - p3.z, a3.w - p3.w);

    out[obase + 0 * HWV]       = v0;
    out[obase + 1 * HWV]       = v1;
    out[obase + 2 * HWV]       = v2;
    out[obase + 3 * HWV]       = v3;
    out[obase + 0 * HWV + HW4] = v0;
    out[obase + 1 * HWV + HW4] = v1;
    out[obase + 2 * HWV + HW4] = v2;
    out[obase + 3 * HWV + HW4] = v3;
}

extern "C" void kernel_launch(void* const* d_in, const int* in_sizes, int n_in,
                              void* d_out, int out_size)
{
    const float4* x = (const float4*)d_in[0];
    float4* out = (float4*)d_out;

    int threads = 256;
    int blocks = TOTALT / threads;   // 2048
    dummyflow_diff_kernel<<<blocks, threads>>>(x, out);
}